// round 1
// baseline (speedup 1.0000x reference)
#include <cuda_runtime.h>
#include <math.h>

#define SDIM 2048
#define DDIM 64
#define QT 64
#define KT 64
#define NT 256
#define KSTR 68   // smem row stride (floats) for Q/K/V: 68 = 4 mod 32 -> conflict-free interleaved reads
#define PSTR 65   // smem row stride for P (scalar access)

// dynamic smem layout: sQ[QT*KSTR] | sK[KT*KSTR] | sV[KT*KSTR] | sP[QT*PSTR]
#define SMEM_FLOATS (QT*KSTR*3 + QT*PSTR)
#define SMEM_BYTES  (SMEM_FLOATS * 4)

__global__ void __launch_bounds__(NT, 2)
fa_fwd(const float* __restrict__ qg_, const float* __restrict__ kg_,
       const float* __restrict__ vg_, float* __restrict__ og_)
{
    extern __shared__ float smem[];
    float* sQ = smem;
    float* sK = sQ + QT * KSTR;
    float* sV = sK + KT * KSTR;
    float* sP = sV + KT * KSTR;

    const int bh = blockIdx.y;
    const int qt = blockIdx.x;
    const size_t base = (size_t)bh * SDIM * DDIM;
    const float* qg = qg_ + base + (size_t)qt * QT * DDIM;
    const float* kg = kg_ + base;
    const float* vg = vg_ + base;
    float*       og = og_ + base + (size_t)qt * QT * DDIM;

    const int tid = threadIdx.x;
    const int r   = tid >> 2;   // 0..63 : query row within tile
    const int sub = tid & 3;    // 0..3  : quad lane

    // Load Q tile, folding softmax scale * log2(e) so probs are exp2f(s - m).
    const float qs = 0.125f * 1.4426950408889634f;  // 1/sqrt(64) * log2(e)
    {
        const float4* src = (const float4*)(qg + r * DDIM + sub * 16);
        float4* dst = (float4*)(sQ + r * KSTR + sub * 16);
        #pragma unroll
        for (int i = 0; i < 4; ++i) {
            float4 a = src[i];
            a.x *= qs; a.y *= qs; a.z *= qs; a.w *= qs;
            dst[i] = a;
        }
    }

    float acc[16];
    #pragma unroll
    for (int i = 0; i < 16; ++i) acc[i] = 0.0f;
    float m = -INFINITY;
    float l = 0.0f;

    for (int j = 0; j < SDIM / KT; ++j) {
        __syncthreads();  // previous tile's PV done reading sV/sP before overwrite
        {
            // coalesced: warp covers 8 contiguous rows (2KB) per ldg.128 sweep
            const float4* ks = (const float4*)(kg + (size_t)j*KT*DDIM + r*DDIM + sub*16);
            const float4* vs = (const float4*)(vg + (size_t)j*KT*DDIM + r*DDIM + sub*16);
            float4* kd = (float4*)(sK + r*KSTR + sub*16);
            float4* vd = (float4*)(sV + r*KSTR + sub*16);
            #pragma unroll
            for (int i = 0; i < 4; ++i) kd[i] = ks[i];
            #pragma unroll
            for (int i = 0; i < 4; ++i) vd[i] = vs[i];
        }
        __syncthreads();

        // ---- QK^T: thread owns score columns c = sub + 4*i (interleaved) ----
        float s[16];
        #pragma unroll
        for (int i = 0; i < 16; ++i) s[i] = 0.0f;
        #pragma unroll
        for (int dd = 0; dd < DDIM; dd += 4) {
            float4 qv = *(const float4*)(sQ + r * KSTR + dd);   // quad-broadcast
            #pragma unroll
            for (int i = 0; i < 16; ++i) {
                float4 kv = *(const float4*)(sK + (sub + 4*i) * KSTR + dd);
                s[i] = fmaf(qv.x, kv.x, s[i]);
                s[i] = fmaf(qv.y, kv.y, s[i]);
                s[i] = fmaf(qv.z, kv.z, s[i]);
                s[i] = fmaf(qv.w, kv.w, s[i]);
            }
        }

        // ---- online softmax (per row, across the 4-lane quad) ----
        float mt = s[0];
        #pragma unroll
        for (int i = 1; i < 16; ++i) mt = fmaxf(mt, s[i]);
        mt = fmaxf(mt, __shfl_xor_sync(0xffffffffu, mt, 1));
        mt = fmaxf(mt, __shfl_xor_sync(0xffffffffu, mt, 2));
        const float mn    = fmaxf(m, mt);
        const float alpha = exp2f(m - mn);   // first tile: exp2f(-inf) = 0
        float ls = 0.0f;
        #pragma unroll
        for (int i = 0; i < 16; ++i) {
            float p = exp2f(s[i] - mn);
            ls += p;
            sP[r * PSTR + sub + 4*i] = p;
        }
        ls += __shfl_xor_sync(0xffffffffu, ls, 1);
        ls += __shfl_xor_sync(0xffffffffu, ls, 2);
        l = l * alpha + ls;
        m = mn;
        #pragma unroll
        for (int i = 0; i < 16; ++i) acc[i] *= alpha;
        __syncwarp();   // sP is quad-local (same warp): order writes before reads

        // ---- PV: thread owns O[r][sub*16 .. sub*16+15] (contiguous d) ----
        #pragma unroll 8
        for (int kk = 0; kk < KT; ++kk) {
            float p = sP[r * PSTR + kk];                      // quad-broadcast
            const float4* vrow = (const float4*)(sV + kk * KSTR + sub * 16);
            float4 v0 = vrow[0], v1 = vrow[1], v2 = vrow[2], v3 = vrow[3];
            acc[0]  = fmaf(p, v0.x, acc[0]);
            acc[1]  = fmaf(p, v0.y, acc[1]);
            acc[2]  = fmaf(p, v0.z, acc[2]);
            acc[3]  = fmaf(p, v0.w, acc[3]);
            acc[4]  = fmaf(p, v1.x, acc[4]);
            acc[5]  = fmaf(p, v1.y, acc[5]);
            acc[6]  = fmaf(p, v1.z, acc[6]);
            acc[7]  = fmaf(p, v1.w, acc[7]);
            acc[8]  = fmaf(p, v2.x, acc[8]);
            acc[9]  = fmaf(p, v2.y, acc[9]);
            acc[10] = fmaf(p, v2.z, acc[10]);
            acc[11] = fmaf(p, v2.w, acc[11]);
            acc[12] = fmaf(p, v3.x, acc[12]);
            acc[13] = fmaf(p, v3.y, acc[13]);
            acc[14] = fmaf(p, v3.z, acc[14]);
            acc[15] = fmaf(p, v3.w, acc[15]);
        }
    }

    // ---- epilogue: normalize and store (coalesced float4) ----
    const float inv = 1.0f / l;
    float4* dst = (float4*)(og + r * DDIM + sub * 16);
    #pragma unroll
    for (int i = 0; i < 4; ++i) {
        float4 a;
        a.x = acc[4*i + 0] * inv;
        a.y = acc[4*i + 1] * inv;
        a.z = acc[4*i + 2] * inv;
        a.w = acc[4*i + 3] * inv;
        dst[i] = a;
    }
}

extern "C" void kernel_launch(void* const* d_in, const int* in_sizes, int n_in,
                              void* d_out, int out_size)
{
    const float* q = (const float*)d_in[0];
    const float* k = (const float*)d_in[1];
    const float* v = (const float*)d_in[2];
    float* out = (float*)d_out;

    // idempotent; host-side func attribute, not a stream op (graph-capture safe)
    cudaFuncSetAttribute(fa_fwd, cudaFuncAttributeMaxDynamicSharedMemorySize, SMEM_BYTES);

    dim3 grid(SDIM / QT, 4 * 16);  // (32 q-tiles, B*H)
    fa_fwd<<<grid, NT, SMEM_BYTES>>>(q, k, v, out);
}

// round 4
// speedup vs baseline: 20.1587x; 20.1587x over previous
#include <cuda_runtime.h>
#include <cstdint>
#include <math.h>

#define SDIM 2048
#define DDIM 64
#define QT 64
#define KT 64
#define NT 128

#define KSTR 68   // banks: row*68 mod 32 = 4*row -> frag reads conflict-free
#define VSTR 72   // banks: row*72 mod 32 = 8*row -> frag reads conflict-free
#define QSTR 68

// smem layout in floats
#define OFF_K  0
#define OFF_V  (64*KSTR)                // 4352
#define OFF_QP (OFF_V + 64*VSTR)        // 8960 (Q staging, then per-warp P buffers)
#define SMEM_FLOATS (OFF_QP + 64*QSTR)  // 13312
#define SMEM_BYTES  (SMEM_FLOATS*4)     // 53248

__device__ __forceinline__ float tf32r(float x){
    float y; asm("cvt.rna.tf32.f32 %0, %1;" : "=f"(y) : "f"(x)); return y;
}
__device__ __forceinline__ float ex2f(float x){
    float y; asm("ex2.approx.ftz.f32 %0, %1;" : "=f"(y) : "f"(x)); return y;
}
__device__ __forceinline__ void mma8(float* d, const float* a, float b0, float b1){
    asm volatile("mma.sync.aligned.m16n8k8.row.col.f32.tf32.tf32.f32 "
                 "{%0,%1,%2,%3},{%4,%5,%6,%7},{%8,%9},{%0,%1,%2,%3};"
                 : "+f"(d[0]),"+f"(d[1]),"+f"(d[2]),"+f"(d[3])
                 : "f"(a[0]),"f"(a[1]),"f"(a[2]),"f"(a[3]),"f"(b0),"f"(b1));
}

__global__ void __launch_bounds__(NT)
fa_mma(const float* __restrict__ qg_, const float* __restrict__ kg_,
       const float* __restrict__ vg_, float* __restrict__ og_)
{
    extern __shared__ float sm[];
    float* sK = sm + OFF_K;
    float* sV = sm + OFF_V;
    float* sQ = sm + OFF_QP;   // Q staging, later per-warp P buffers (same rows)

    const int tid  = threadIdx.x;
    const int wid  = tid >> 5;
    const int lane = tid & 31;
    const int g    = lane >> 2;   // groupID 0..7
    const int q    = lane & 3;    // threadID-in-group 0..3
    const int ra   = wid * 16 + g;   // this thread's first q-row in tile
    // second row is ra+8

    const int bh = blockIdx.y;
    const int qt = blockIdx.x;
    const size_t base = (size_t)bh * SDIM * DDIM;
    const float* qg = qg_ + base + (size_t)qt * QT * DDIM;
    const float* kg = kg_ + base;
    const float* vg = vg_ + base;
    float*       og = og_ + base + (size_t)qt * QT * DDIM;

    // ---- stage Q tile (scale * log2e folded, tf32-rounded) ----
    const float qs = 0.125f * 1.44269504088896340736f;
    for (int i = tid; i < QT * DDIM / 4; i += NT) {
        int row = i >> 4, c4 = i & 15;
        float4 a = ((const float4*)qg)[i];
        a.x = tf32r(a.x * qs); a.y = tf32r(a.y * qs);
        a.z = tf32r(a.z * qs); a.w = tf32r(a.w * qs);
        *(float4*)&sQ[row * QSTR + c4 * 4] = a;
    }
    __syncthreads();

    // ---- Q fragments -> registers (persist whole kernel) ----
    float qf[8][4];
    #pragma unroll
    for (int kb = 0; kb < 8; ++kb) {
        qf[kb][0] = sQ[(ra    ) * QSTR + kb*8 + q    ];
        qf[kb][1] = sQ[(ra + 8) * QSTR + kb*8 + q    ];
        qf[kb][2] = sQ[(ra    ) * QSTR + kb*8 + q + 4];
        qf[kb][3] = sQ[(ra + 8) * QSTR + kb*8 + q + 4];
    }
    // After this, each warp reads/writes ONLY rows [wid*16, wid*16+16) of sQ (its P buffer).

    float o[8][4];
    #pragma unroll
    for (int nb = 0; nb < 8; ++nb) { o[nb][0]=0.f; o[nb][1]=0.f; o[nb][2]=0.f; o[nb][3]=0.f; }
    float ma = -INFINITY, mb = -INFINITY, la = 0.f, lb = 0.f;

    for (int j = 0; j < SDIM / KT; ++j) {
        __syncthreads();   // prior tile's K/V reads complete
        {
            const float4* kp = (const float4*)(kg + (size_t)j * KT * DDIM);
            const float4* vp = (const float4*)(vg + (size_t)j * KT * DDIM);
            for (int i = tid; i < KT * DDIM / 4; i += NT) {
                int row = i >> 4, c4 = i & 15;
                float4 kv = kp[i];
                kv.x = tf32r(kv.x); kv.y = tf32r(kv.y); kv.z = tf32r(kv.z); kv.w = tf32r(kv.w);
                *(float4*)&sK[row * KSTR + c4 * 4] = kv;
                float4 vv = vp[i];
                vv.x = tf32r(vv.x); vv.y = tf32r(vv.y); vv.z = tf32r(vv.z); vv.w = tf32r(vv.w);
                *(float4*)&sV[row * VSTR + c4 * 4] = vv;
            }
        }
        __syncthreads();

        // ---- S = Q @ K^T : 8 kb x 8 nb, 8 independent accumulator chains ----
        float c[8][4];
        #pragma unroll
        for (int nb = 0; nb < 8; ++nb) { c[nb][0]=0.f; c[nb][1]=0.f; c[nb][2]=0.f; c[nb][3]=0.f; }
        #pragma unroll
        for (int kb = 0; kb < 8; ++kb) {
            #pragma unroll
            for (int nb = 0; nb < 8; ++nb) {
                float b0 = sK[(nb*8 + g) * KSTR + kb*8 + q    ];
                float b1 = sK[(nb*8 + g) * KSTR + kb*8 + q + 4];
                mma8(c[nb], qf[kb], b0, b1);
            }
        }

        // ---- online softmax: thread owns rows ra (c0,c1) and ra+8 (c2,c3) ----
        float mta = -INFINITY, mtb = -INFINITY;
        #pragma unroll
        for (int nb = 0; nb < 8; ++nb) {
            mta = fmaxf(mta, fmaxf(c[nb][0], c[nb][1]));
            mtb = fmaxf(mtb, fmaxf(c[nb][2], c[nb][3]));
        }
        mta = fmaxf(mta, __shfl_xor_sync(0xffffffffu, mta, 1));
        mta = fmaxf(mta, __shfl_xor_sync(0xffffffffu, mta, 2));
        mtb = fmaxf(mtb, __shfl_xor_sync(0xffffffffu, mtb, 1));
        mtb = fmaxf(mtb, __shfl_xor_sync(0xffffffffu, mtb, 2));
        const float mna = fmaxf(ma, mta);
        const float mnb = fmaxf(mb, mtb);
        const float aa = ex2f(ma - mna);       // first tile: 0
        const float ab = ex2f(mb - mnb);
        float lsa = 0.f, lsb = 0.f;
        #pragma unroll
        for (int nb = 0; nb < 8; ++nb) {
            float p0 = ex2f(c[nb][0] - mna);
            float p1 = ex2f(c[nb][1] - mna);
            float p2 = ex2f(c[nb][2] - mnb);
            float p3 = ex2f(c[nb][3] - mnb);
            lsa += p0 + p1; lsb += p2 + p3;
            c[nb][0] = p0; c[nb][1] = p1; c[nb][2] = p2; c[nb][3] = p3;
        }
        lsa += __shfl_xor_sync(0xffffffffu, lsa, 1);
        lsa += __shfl_xor_sync(0xffffffffu, lsa, 2);
        lsb += __shfl_xor_sync(0xffffffffu, lsb, 1);
        lsb += __shfl_xor_sync(0xffffffffu, lsb, 2);
        ma = mna; mb = mnb;
        la = la * aa + lsa;
        lb = lb * ab + lsb;

        // ---- rescale O accumulators ----
        #pragma unroll
        for (int nb = 0; nb < 8; ++nb) {
            o[nb][0] *= aa; o[nb][1] *= aa;
            o[nb][2] *= ab; o[nb][3] *= ab;
        }

        // ---- P -> per-warp smem buffer (tf32-rounded) ----
        #pragma unroll
        for (int nb = 0; nb < 8; ++nb) {
            float2 pA; pA.x = tf32r(c[nb][0]); pA.y = tf32r(c[nb][1]);
            float2 pB; pB.x = tf32r(c[nb][2]); pB.y = tf32r(c[nb][3]);
            *(float2*)&sQ[(ra    ) * QSTR + nb*8 + 2*q] = pA;
            *(float2*)&sQ[(ra + 8) * QSTR + nb*8 + 2*q] = pB;
        }
        __syncwarp();

        // ---- O += P @ V : A-frag from P smem, B-frag from V smem ----
        #pragma unroll
        for (int kb = 0; kb < 8; ++kb) {
            float a_[4];
            a_[0] = sQ[(ra    ) * QSTR + kb*8 + q    ];
            a_[1] = sQ[(ra + 8) * QSTR + kb*8 + q    ];
            a_[2] = sQ[(ra    ) * QSTR + kb*8 + q + 4];
            a_[3] = sQ[(ra + 8) * QSTR + kb*8 + q + 4];
            #pragma unroll
            for (int nb = 0; nb < 8; ++nb) {
                float b0 = sV[(kb*8 + q    ) * VSTR + nb*8 + g];
                float b1 = sV[(kb*8 + q + 4) * VSTR + nb*8 + g];
                mma8(o[nb], a_, b0, b1);
            }
        }
        __syncwarp();   // P buffer reads done before next tile's softmax overwrites
    }

    // ---- epilogue: normalize, store ----
    const float inva = 1.0f / la;
    const float invb = 1.0f / lb;
    #pragma unroll
    for (int nb = 0; nb < 8; ++nb) {
        float2 sa; sa.x = o[nb][0] * inva; sa.y = o[nb][1] * inva;
        float2 sb; sb.x = o[nb][2] * invb; sb.y = o[nb][3] * invb;
        *(float2*)&og[(size_t)(ra    ) * DDIM + nb*8 + 2*q] = sa;
        *(float2*)&og[(size_t)(ra + 8) * DDIM + nb*8 + 2*q] = sb;
    }
}

extern "C" void kernel_launch(void* const* d_in, const int* in_sizes, int n_in,
                              void* d_out, int out_size)
{
    const float* q = (const float*)d_in[0];
    const float* k = (const float*)d_in[1];
    const float* v = (const float*)d_in[2];
    float* out = (float*)d_out;

    cudaFuncSetAttribute(fa_mma, cudaFuncAttributeMaxDynamicSharedMemorySize, SMEM_BYTES);

    dim3 grid(SDIM / QT, 4 * 16);   // (32 q-tiles, B*H = 64)
    fa_mma<<<grid, NT, SMEM_BYTES>>>(q, k, v, out);
}

// round 5
// speedup vs baseline: 21.7809x; 1.0805x over previous
#include <cuda_runtime.h>
#include <cstdint>
#include <math.h>

#define SDIM 2048
#define DDIM 64
#define QT 128
#define KT 64
#define NT 128

#define KSTR 68   // row*68 mod 32 banks = 4*row -> LDSM tiles + frag reads conflict-free
#define VSTR 72   // (8q+g) bank pattern -> scalar V frag reads conflict-free
#define PSTR 68

// smem layout (floats): sK | sV | sP (P buffers; Q staged here pre-loop)
#define OFF_K 0
#define OFF_V (KT*KSTR)                 // 4352
#define OFF_P (OFF_V + KT*VSTR)        // 8960
#define SMEM_FLOATS (OFF_P + QT*PSTR)  // 17664
#define SMEM_BYTES  (SMEM_FLOATS*4)    // 70656

__device__ __forceinline__ float tf32r(float x){
    float y; asm("cvt.rna.tf32.f32 %0, %1;" : "=f"(y) : "f"(x)); return y;
}
__device__ __forceinline__ float ex2f(float x){
    float y; asm("ex2.approx.ftz.f32 %0, %1;" : "=f"(y) : "f"(x)); return y;
}
__device__ __forceinline__ uint32_t smem_u32(const void* p){
    uint32_t a;
    asm("{ .reg .u64 t; cvta.to.shared.u64 t, %1; cvt.u32.u64 %0, t; }":"=r"(a):"l"(p));
    return a;
}
__device__ __forceinline__ void mma8(float* d, const float* a, float b0, float b1){
    asm volatile("mma.sync.aligned.m16n8k8.row.col.f32.tf32.tf32.f32 "
                 "{%0,%1,%2,%3},{%4,%5,%6,%7},{%8,%9},{%0,%1,%2,%3};"
                 : "+f"(d[0]),"+f"(d[1]),"+f"(d[2]),"+f"(d[3])
                 : "f"(a[0]),"f"(a[1]),"f"(a[2]),"f"(a[3]),"f"(b0),"f"(b1));
}
__device__ __forceinline__ void ldsm4(uint32_t addr, uint32_t* r){
    asm volatile("ldmatrix.sync.aligned.m8n8.x4.shared.b16 {%0,%1,%2,%3}, [%4];"
                 : "=r"(r[0]),"=r"(r[1]),"=r"(r[2]),"=r"(r[3]) : "r"(addr));
}

__global__ void __launch_bounds__(NT)
fa_mma(const float* __restrict__ qg_, const float* __restrict__ kg_,
       const float* __restrict__ vg_, float* __restrict__ og_)
{
    extern __shared__ float sm[];
    float* sK = sm + OFF_K;
    float* sV = sm + OFF_V;
    float* sP = sm + OFF_P;
    const uint32_t sb = smem_u32(sm);

    const int tid  = threadIdx.x;
    const int wid  = tid >> 5;
    const int lane = tid & 31;
    const int g    = lane >> 2;
    const int q    = lane & 3;
    const int wbase = wid * 32;      // warp owns q-rows [wbase, wbase+32)

    const int bh = blockIdx.y;
    const int qt = blockIdx.x;
    const size_t base = (size_t)bh * SDIM * DDIM;
    const float* qg = qg_ + base + (size_t)qt * QT * DDIM;
    const float* kg = kg_ + base;
    const float* vg = vg_ + base;
    float*       og = og_ + base + (size_t)qt * QT * DDIM;

    // ---- stage Q into sP region (scale*log2e folded, tf32-rounded) ----
    const float qs = 0.125f * 1.44269504088896340736f;
    for (int i = tid; i < QT * DDIM / 4; i += NT) {
        int row = i >> 4, c4 = i & 15;
        float4 a = ((const float4*)qg)[i];
        a.x = tf32r(a.x * qs); a.y = tf32r(a.y * qs);
        a.z = tf32r(a.z * qs); a.w = tf32r(a.w * qs);
        *(float4*)&sP[row * PSTR + c4 * 4] = a;
    }
    __syncthreads();

    // ---- Q fragments -> registers (persist; m32 = 2 m16 blocks per warp) ----
    float qf[8][2][4];
    #pragma unroll
    for (int kb = 0; kb < 8; ++kb) {
        #pragma unroll
        for (int blk = 0; blk < 2; ++blk) {
            const int r0 = wbase + blk * 16 + g;
            qf[kb][blk][0] = sP[(r0    ) * PSTR + kb*8 + q    ];
            qf[kb][blk][1] = sP[(r0 + 8) * PSTR + kb*8 + q    ];
            qf[kb][blk][2] = sP[(r0    ) * PSTR + kb*8 + q + 4];
            qf[kb][blk][3] = sP[(r0 + 8) * PSTR + kb*8 + q + 4];
        }
    }
    __syncthreads();

    float o[2][8][4];
    #pragma unroll
    for (int blk = 0; blk < 2; ++blk)
        #pragma unroll
        for (int nb = 0; nb < 8; ++nb)
            { o[blk][nb][0]=0.f; o[blk][nb][1]=0.f; o[blk][nb][2]=0.f; o[blk][nb][3]=0.f; }
    float mx[2][2] = {{-INFINITY,-INFINITY},{-INFINITY,-INFINITY}};
    float lx[2][2] = {{0.f,0.f},{0.f,0.f}};

    // ---- per-lane LDSM base addresses ----
    // QK B (K tile): x4 = {nb_even k0-3, nb_even k4-7, nb_odd k0-3, nb_odd k4-7}
    const int qk_nrow = ((lane >> 4) << 3) + (lane & 7);   // row within 2-nb pair block
    const int qk_kh   = ((lane >> 3) & 1) << 2;            // k half (0 or 4)
    const uint32_t aKb = sb + (uint32_t)((OFF_K + qk_nrow * KSTR + qk_kh) * 4);
    // PV A (P tile): x4 = {rows0-7 k0-3, rows8-15 k0-3, rows0-7 k4-7, rows8-15 k4-7}
    const int pa_row = (((lane >> 3) & 1) << 3) + (lane & 7);
    const int pa_kh  = (lane >> 4) << 2;
    const uint32_t aPb = sb + (uint32_t)((OFF_P + (wbase + pa_row) * PSTR + pa_kh) * 4);

    for (int j = 0; j < SDIM / KT; ++j) {
        __syncthreads();   // prior tile's sK/sV reads complete
        {
            const float4* kp = (const float4*)(kg + (size_t)j * KT * DDIM);
            const float4* vp = (const float4*)(vg + (size_t)j * KT * DDIM);
            for (int i = tid; i < KT * DDIM / 4; i += NT) {
                int row = i >> 4, c4 = i & 15;
                float4 kv = kp[i];
                kv.x = tf32r(kv.x); kv.y = tf32r(kv.y); kv.z = tf32r(kv.z); kv.w = tf32r(kv.w);
                *(float4*)&sK[row * KSTR + c4 * 4] = kv;
                float4 vv = vp[i];
                vv.x = tf32r(vv.x); vv.y = tf32r(vv.y); vv.z = tf32r(vv.z); vv.w = tf32r(vv.w);
                *(float4*)&sV[row * VSTR + c4 * 4] = vv;
            }
        }
        __syncthreads();

        // ---- per 16-row block: S = Q@K^T, online softmax, P -> smem ----
        #pragma unroll
        for (int blk = 0; blk < 2; ++blk) {
            float c[8][4];
            #pragma unroll
            for (int nb = 0; nb < 8; ++nb)
                { c[nb][0]=0.f; c[nb][1]=0.f; c[nb][2]=0.f; c[nb][3]=0.f; }
            #pragma unroll
            for (int kb = 0; kb < 8; ++kb) {
                #pragma unroll
                for (int p = 0; p < 4; ++p) {   // covers nb = 2p, 2p+1
                    uint32_t r[4];
                    ldsm4(aKb + (uint32_t)(((p*16) * KSTR + kb*8) * 4), r);
                    mma8(c[2*p  ], qf[kb][blk], __uint_as_float(r[0]), __uint_as_float(r[1]));
                    mma8(c[2*p+1], qf[kb][blk], __uint_as_float(r[2]), __uint_as_float(r[3]));
                }
            }

            float mtA = -INFINITY, mtB = -INFINITY;
            #pragma unroll
            for (int nb = 0; nb < 8; ++nb) {
                mtA = fmaxf(mtA, fmaxf(c[nb][0], c[nb][1]));
                mtB = fmaxf(mtB, fmaxf(c[nb][2], c[nb][3]));
            }
            mtA = fmaxf(mtA, __shfl_xor_sync(0xffffffffu, mtA, 1));
            mtA = fmaxf(mtA, __shfl_xor_sync(0xffffffffu, mtA, 2));
            mtB = fmaxf(mtB, __shfl_xor_sync(0xffffffffu, mtB, 1));
            mtB = fmaxf(mtB, __shfl_xor_sync(0xffffffffu, mtB, 2));
            const float mnA = fmaxf(mx[blk][0], mtA);
            const float mnB = fmaxf(mx[blk][1], mtB);
            const float aA  = ex2f(mx[blk][0] - mnA);
            const float aB  = ex2f(mx[blk][1] - mnB);
            float lsA = 0.f, lsB = 0.f;
            const int rA = wbase + blk * 16 + g;
            #pragma unroll
            for (int nb = 0; nb < 8; ++nb) {
                float p0 = ex2f(c[nb][0] - mnA);
                float p1 = ex2f(c[nb][1] - mnA);
                float p2 = ex2f(c[nb][2] - mnB);
                float p3 = ex2f(c[nb][3] - mnB);
                lsA += p0 + p1; lsB += p2 + p3;
                float2 fa; fa.x = tf32r(p0); fa.y = tf32r(p1);
                float2 fb; fb.x = tf32r(p2); fb.y = tf32r(p3);
                *(float2*)&sP[(rA    ) * PSTR + nb*8 + 2*q] = fa;
                *(float2*)&sP[(rA + 8) * PSTR + nb*8 + 2*q] = fb;
            }
            lsA += __shfl_xor_sync(0xffffffffu, lsA, 1);
            lsA += __shfl_xor_sync(0xffffffffu, lsA, 2);
            lsB += __shfl_xor_sync(0xffffffffu, lsB, 1);
            lsB += __shfl_xor_sync(0xffffffffu, lsB, 2);
            mx[blk][0] = mnA; mx[blk][1] = mnB;
            lx[blk][0] = lx[blk][0] * aA + lsA;
            lx[blk][1] = lx[blk][1] * aB + lsB;
            #pragma unroll
            for (int nb = 0; nb < 8; ++nb) {
                o[blk][nb][0] *= aA; o[blk][nb][1] *= aA;
                o[blk][nb][2] *= aB; o[blk][nb][3] *= aB;
            }
        }
        __syncwarp();   // P stores visible to all lanes before LDSM reads

        // ---- O += P @ V : A via LDSM from sP, B scalar (reused across blks) ----
        #pragma unroll
        for (int kb = 0; kb < 8; ++kb) {
            uint32_t u0[4], u1[4];
            ldsm4(aPb + (uint32_t)((kb*8) * 4), u0);
            ldsm4(aPb + (uint32_t)((16 * PSTR + kb*8) * 4), u1);
            float a0[4], a1[4];
            #pragma unroll
            for (int t = 0; t < 4; ++t) { a0[t] = __uint_as_float(u0[t]); a1[t] = __uint_as_float(u1[t]); }
            #pragma unroll
            for (int nb = 0; nb < 8; ++nb) {
                float b0 = sV[(kb*8 + q    ) * VSTR + nb*8 + g];
                float b1 = sV[(kb*8 + q + 4) * VSTR + nb*8 + g];
                mma8(o[0][nb], a0, b0, b1);
                mma8(o[1][nb], a1, b0, b1);
            }
        }
        __syncwarp();   // PV cross-lane reads of sP done before next tile overwrites
    }

    // ---- epilogue: normalize, store ----
    #pragma unroll
    for (int blk = 0; blk < 2; ++blk) {
        const float invA = 1.0f / lx[blk][0];
        const float invB = 1.0f / lx[blk][1];
        const int rA = wbase + blk * 16 + g;
        #pragma unroll
        for (int nb = 0; nb < 8; ++nb) {
            float2 sa; sa.x = o[blk][nb][0] * invA; sa.y = o[blk][nb][1] * invA;
            float2 sb2; sb2.x = o[blk][nb][2] * invB; sb2.y = o[blk][nb][3] * invB;
            *(float2*)&og[(size_t)(rA    ) * DDIM + nb*8 + 2*q] = sa;
            *(float2*)&og[(size_t)(rA + 8) * DDIM + nb*8 + 2*q] = sb2;
        }
    }
}

extern "C" void kernel_launch(void* const* d_in, const int* in_sizes, int n_in,
                              void* d_out, int out_size)
{
    const float* q = (const float*)d_in[0];
    const float* k = (const float*)d_in[1];
    const float* v = (const float*)d_in[2];
    float* out = (float*)d_out;

    cudaFuncSetAttribute(fa_mma, cudaFuncAttributeMaxDynamicSharedMemorySize, SMEM_BYTES);

    dim3 grid(SDIM / QT, 4 * 16);   // (16 q-tiles, B*H = 64)
    fa_mma<<<grid, NT, SMEM_BYTES>>>(q, k, v, out);
}

// round 6
// speedup vs baseline: 24.8375x; 1.1403x over previous
#include <cuda_runtime.h>
#include <cstdint>
#include <math.h>

#define SDIM 2048
#define DDIM 64
#define QT 128
#define KT 64
#define NT 128

#define STR 68   // shared row stride (floats): 272B rows -> ldsm rows hit distinct bank-quads

// smem layout (floats): sK[64][68] | sVt[64][68] (V transposed: rows=d, cols=kv) | sP[128][68]
#define OFF_K  0
#define OFF_VT (KT*STR)                  // 4352
#define OFF_P  (OFF_VT + DDIM*STR)       // 8704
#define SMEM_FLOATS (OFF_P + QT*STR)     // 17408
#define SMEM_BYTES  (SMEM_FLOATS*4)      // 69632

__device__ __forceinline__ float tf32r(float x){
    float y; asm("cvt.rna.tf32.f32 %0, %1;" : "=f"(y) : "f"(x)); return y;
}
__device__ __forceinline__ float ex2f(float x){
    float y; asm("ex2.approx.ftz.f32 %0, %1;" : "=f"(y) : "f"(x)); return y;
}
__device__ __forceinline__ uint32_t smem_u32(const void* p){
    uint32_t a;
    asm("{ .reg .u64 t; cvta.to.shared.u64 t, %1; cvt.u32.u64 %0, t; }":"=r"(a):"l"(p));
    return a;
}
__device__ __forceinline__ void mma8(float* d, const float* a, float b0, float b1){
    asm volatile("mma.sync.aligned.m16n8k8.row.col.f32.tf32.tf32.f32 "
                 "{%0,%1,%2,%3},{%4,%5,%6,%7},{%8,%9},{%0,%1,%2,%3};"
                 : "+f"(d[0]),"+f"(d[1]),"+f"(d[2]),"+f"(d[3])
                 : "f"(a[0]),"f"(a[1]),"f"(a[2]),"f"(a[3]),"f"(b0),"f"(b1));
}
__device__ __forceinline__ void ldsm4(uint32_t addr, uint32_t* r){
    asm volatile("ldmatrix.sync.aligned.m8n8.x4.shared.b16 {%0,%1,%2,%3}, [%4];"
                 : "=r"(r[0]),"=r"(r[1]),"=r"(r[2]),"=r"(r[3]) : "r"(addr));
}

__global__ void __launch_bounds__(NT, 2)
fa_mma(const float* __restrict__ qg_, const float* __restrict__ kg_,
       const float* __restrict__ vg_, float* __restrict__ og_)
{
    extern __shared__ float sm[];
    float* sK  = sm + OFF_K;
    float* sVt = sm + OFF_VT;
    float* sP  = sm + OFF_P;
    const uint32_t sb = smem_u32(sm);

    const int tid  = threadIdx.x;
    const int wid  = tid >> 5;
    const int lane = tid & 31;
    const int g    = lane >> 2;
    const int q    = lane & 3;
    const int wbase = wid * 32;      // warp owns q-rows [wbase, wbase+32)

    const int bh = blockIdx.y;
    const int qt = blockIdx.x;
    const size_t base = (size_t)bh * SDIM * DDIM;
    const float* qg = qg_ + base + (size_t)qt * QT * DDIM;
    const float* kg = kg_ + base;
    const float* vg = vg_ + base;
    float*       og = og_ + base + (size_t)qt * QT * DDIM;

    // ---- stage Q into sP (scale*log2e folded, tf32-rounded) ----
    const float qs = 0.125f * 1.44269504088896340736f;
    for (int i = tid; i < QT * DDIM / 4; i += NT) {
        int row = i >> 4, c4 = i & 15;
        float4 a = ((const float4*)qg)[i];
        a.x = tf32r(a.x * qs); a.y = tf32r(a.y * qs);
        a.z = tf32r(a.z * qs); a.w = tf32r(a.w * qs);
        *(float4*)&sP[row * STR + c4 * 4] = a;
    }
    __syncthreads();

    // ---- Q fragments -> registers (persist; m32 = 2 m16 blocks per warp) ----
    float qf[8][2][4];
    #pragma unroll
    for (int kb = 0; kb < 8; ++kb) {
        #pragma unroll
        for (int blk = 0; blk < 2; ++blk) {
            const int r0 = wbase + blk * 16 + g;
            qf[kb][blk][0] = sP[(r0    ) * STR + kb*8 + q    ];
            qf[kb][blk][1] = sP[(r0 + 8) * STR + kb*8 + q    ];
            qf[kb][blk][2] = sP[(r0    ) * STR + kb*8 + q + 4];
            qf[kb][blk][3] = sP[(r0 + 8) * STR + kb*8 + q + 4];
        }
    }
    __syncthreads();

    float o[2][8][4];
    #pragma unroll
    for (int blk = 0; blk < 2; ++blk)
        #pragma unroll
        for (int nb = 0; nb < 8; ++nb)
            { o[blk][nb][0]=0.f; o[blk][nb][1]=0.f; o[blk][nb][2]=0.f; o[blk][nb][3]=0.f; }
    float mx[2][2] = {{-INFINITY,-INFINITY},{-INFINITY,-INFINITY}};
    float lx[2][2] = {{0.f,0.f},{0.f,0.f}};

    // ---- per-lane LDSM base addresses (B-frag pattern, shared by K and Vt) ----
    // x4 tiles = {nb_even kh0, nb_even kh1, nb_odd kh0, nb_odd kh1}
    const int b_nrow = ((lane >> 4) << 3) + (lane & 7);
    const int b_kh   = ((lane >> 3) & 1) << 2;
    const uint32_t aKb = sb + (uint32_t)((OFF_K  + b_nrow * STR + b_kh) * 4);
    const uint32_t aVb = sb + (uint32_t)((OFF_VT + b_nrow * STR + b_kh) * 4);
    // PV A (P tile): x4 = {rows0-7 kh0, rows8-15 kh0, rows0-7 kh1, rows8-15 kh1}
    const int pa_row = (((lane >> 3) & 1) << 3) + (lane & 7);
    const int pa_kh  = (lane >> 4) << 2;
    const uint32_t aPb = sb + (uint32_t)((OFF_P + (wbase + pa_row) * STR + pa_kh) * 4);

    // V staging thread mapping: lanes sweep d (coalesced LDG.32), transpose into sVt
    const int v_dlo = lane;            // d = v_dlo + 32*h
    const int v_kv0 = (wid) * 4;       // kv = v_kv0 + 16*jj .. +3

    for (int j = 0; j < SDIM / KT; ++j) {
        __syncthreads();   // prior tile's sK/sVt reads complete
        {
            // K: [kv][d] row-major, tf32-rounded, stride 68
            const float4* kp = (const float4*)(kg + (size_t)j * KT * DDIM);
            #pragma unroll
            for (int it = 0; it < 8; ++it) {
                int i = tid + it * NT;
                int row = i >> 4, c4 = i & 15;
                float4 kv = kp[i];
                kv.x = tf32r(kv.x); kv.y = tf32r(kv.y); kv.z = tf32r(kv.z); kv.w = tf32r(kv.w);
                *(float4*)&sK[row * STR + c4 * 4] = kv;
            }
            // V: transpose to sVt[d][kv], tf32-rounded
            const float* vt = vg + (size_t)j * KT * DDIM;
            #pragma unroll
            for (int h = 0; h < 2; ++h) {
                const int d = v_dlo + 32 * h;
                #pragma unroll
                for (int jj = 0; jj < 4; ++jj) {
                    const int kv0 = v_kv0 + 16 * jj;
                    float4 w;
                    w.x = tf32r(vt[(size_t)(kv0 + 0) * DDIM + d]);
                    w.y = tf32r(vt[(size_t)(kv0 + 1) * DDIM + d]);
                    w.z = tf32r(vt[(size_t)(kv0 + 2) * DDIM + d]);
                    w.w = tf32r(vt[(size_t)(kv0 + 3) * DDIM + d]);
                    *(float4*)&sVt[d * STR + kv0] = w;
                }
            }
        }
        __syncthreads();

        // ---- per 16-row block: S = Q@K^T, online softmax, P -> smem ----
        #pragma unroll
        for (int blk = 0; blk < 2; ++blk) {
            float c[8][4];
            #pragma unroll
            for (int nb = 0; nb < 8; ++nb)
                { c[nb][0]=0.f; c[nb][1]=0.f; c[nb][2]=0.f; c[nb][3]=0.f; }
            #pragma unroll
            for (int kb = 0; kb < 8; ++kb) {
                #pragma unroll
                for (int p = 0; p < 4; ++p) {
                    uint32_t r[4];
                    ldsm4(aKb + (uint32_t)(((p*16) * STR + kb*8) * 4), r);
                    mma8(c[2*p  ], qf[kb][blk], __uint_as_float(r[0]), __uint_as_float(r[1]));
                    mma8(c[2*p+1], qf[kb][blk], __uint_as_float(r[2]), __uint_as_float(r[3]));
                }
            }

            float mtA = -INFINITY, mtB = -INFINITY;
            #pragma unroll
            for (int nb = 0; nb < 8; ++nb) {
                mtA = fmaxf(mtA, fmaxf(c[nb][0], c[nb][1]));
                mtB = fmaxf(mtB, fmaxf(c[nb][2], c[nb][3]));
            }
            mtA = fmaxf(mtA, __shfl_xor_sync(0xffffffffu, mtA, 1));
            mtA = fmaxf(mtA, __shfl_xor_sync(0xffffffffu, mtA, 2));
            mtB = fmaxf(mtB, __shfl_xor_sync(0xffffffffu, mtB, 1));
            mtB = fmaxf(mtB, __shfl_xor_sync(0xffffffffu, mtB, 2));
            const float mnA = fmaxf(mx[blk][0], mtA);
            const float mnB = fmaxf(mx[blk][1], mtB);
            const float aA  = ex2f(mx[blk][0] - mnA);
            const float aB  = ex2f(mx[blk][1] - mnB);
            float lsA = 0.f, lsB = 0.f;
            const int rA = wbase + blk * 16 + g;
            #pragma unroll
            for (int nb = 0; nb < 8; ++nb) {
                float p0 = ex2f(c[nb][0] - mnA);
                float p1 = ex2f(c[nb][1] - mnA);
                float p2 = ex2f(c[nb][2] - mnB);
                float p3 = ex2f(c[nb][3] - mnB);
                lsA += p0 + p1; lsB += p2 + p3;
                float2 fa; fa.x = tf32r(p0); fa.y = tf32r(p1);
                float2 fb; fb.x = tf32r(p2); fb.y = tf32r(p3);
                *(float2*)&sP[(rA    ) * STR + nb*8 + 2*q] = fa;
                *(float2*)&sP[(rA + 8) * STR + nb*8 + 2*q] = fb;
            }
            lsA += __shfl_xor_sync(0xffffffffu, lsA, 1);
            lsA += __shfl_xor_sync(0xffffffffu, lsA, 2);
            lsB += __shfl_xor_sync(0xffffffffu, lsB, 1);
            lsB += __shfl_xor_sync(0xffffffffu, lsB, 2);
            mx[blk][0] = mnA; mx[blk][1] = mnB;
            lx[blk][0] = lx[blk][0] * aA + lsA;
            lx[blk][1] = lx[blk][1] * aB + lsB;
            #pragma unroll
            for (int nb = 0; nb < 8; ++nb) {
                o[blk][nb][0] *= aA; o[blk][nb][1] *= aA;
                o[blk][nb][2] *= aB; o[blk][nb][3] *= aB;
            }
        }
        __syncwarp();   // P stores visible to all lanes before LDSM reads

        // ---- O += P @ V : A via LDSM from sP, B via LDSM from sVt ----
        #pragma unroll
        for (int kb = 0; kb < 8; ++kb) {
            uint32_t u0[4], u1[4];
            ldsm4(aPb + (uint32_t)((kb*8) * 4), u0);
            ldsm4(aPb + (uint32_t)((16 * STR + kb*8) * 4), u1);
            float a0[4], a1[4];
            #pragma unroll
            for (int t = 0; t < 4; ++t) { a0[t] = __uint_as_float(u0[t]); a1[t] = __uint_as_float(u1[t]); }
            #pragma unroll
            for (int p = 0; p < 4; ++p) {
                uint32_t rv[4];
                ldsm4(aVb + (uint32_t)(((p*16) * STR + kb*8) * 4), rv);
                const float b0 = __uint_as_float(rv[0]);
                const float b1 = __uint_as_float(rv[1]);
                const float b2 = __uint_as_float(rv[2]);
                const float b3 = __uint_as_float(rv[3]);
                mma8(o[0][2*p  ], a0, b0, b1);
                mma8(o[0][2*p+1], a0, b2, b3);
                mma8(o[1][2*p  ], a1, b0, b1);
                mma8(o[1][2*p+1], a1, b2, b3);
            }
        }
        __syncwarp();   // PV cross-lane reads of sP/sVt done before next tile overwrites
    }

    // ---- epilogue: normalize, store ----
    #pragma unroll
    for (int blk = 0; blk < 2; ++blk) {
        const float invA = 1.0f / lx[blk][0];
        const float invB = 1.0f / lx[blk][1];
        const int rA = wbase + blk * 16 + g;
        #pragma unroll
        for (int nb = 0; nb < 8; ++nb) {
            float2 sa; sa.x = o[blk][nb][0] * invA; sa.y = o[blk][nb][1] * invA;
            float2 sb2; sb2.x = o[blk][nb][2] * invB; sb2.y = o[blk][nb][3] * invB;
            *(float2*)&og[(size_t)(rA    ) * DDIM + nb*8 + 2*q] = sa;
            *(float2*)&og[(size_t)(rA + 8) * DDIM + nb*8 + 2*q] = sb2;
        }
    }
}

extern "C" void kernel_launch(void* const* d_in, const int* in_sizes, int n_in,
                              void* d_out, int out_size)
{
    const float* q = (const float*)d_in[0];
    const float* k = (const float*)d_in[1];
    const float* v = (const float*)d_in[2];
    float* out = (float*)d_out;

    cudaFuncSetAttribute(fa_mma, cudaFuncAttributeMaxDynamicSharedMemorySize, SMEM_BYTES);

    dim3 grid(SDIM / QT, 4 * 16);   // (16 q-tiles, B*H = 64)
    fa_mma<<<grid, NT, SMEM_BYTES>>>(q, k, v, out);
}